// round 11
// baseline (speedup 1.0000x reference)
#include <cuda_runtime.h>
#include <math.h>

// Shapes fixed: x (4,64,128,128), k (4,64,25,25), alpha (1,64,1,1), sf=2.
// Output (4,64,256,256) fp32.
#define NPLANES 256
#define NCH 64
#define HSTRIDE (129 * 256)   // half-spectrum plane stride (rows 0..128)

__device__ float2 g_SA[NPLANES * HSTRIDE];     // FB half
__device__ float2 g_SB[NPLANES * HSTRIDE];     // G half
__device__ float2 g_SC[NPLANES * 128 * 128];   // Fx^T

#define SP(i) ((i) + ((i) >> 4))
#define SP8(i) ((i) + ((i) >> 3))

// twiddle value: e^{-2 pi i t/256}
__device__ __forceinline__ float2 twval(int t) {
    float s, c;
    sincospif(-(float)t * (1.0f / 128.0f), &s, &c);
    return make_float2(c, s);
}

__device__ __forceinline__ float2 cmulf(float2 a, float2 b) {
    return make_float2(a.x * b.x - a.y * b.y, a.x * b.y + a.y * b.x);
}
__device__ __forceinline__ float2 cadd(float2 a, float2 b) {
    return make_float2(a.x + b.x, a.y + b.y);
}
__device__ __forceinline__ float2 csub(float2 a, float2 b) {
    return make_float2(a.x - b.x, a.y - b.y);
}

template <bool INV>
__device__ __forceinline__ float2 twmul(float2 a, float2 w) {
    float wy = INV ? -w.y : w.y;
    return make_float2(a.x * w.x - a.y * wy, a.x * wy + a.y * w.x);
}

// complex mul by compile-time constant (forward sign); conj for INV
template <bool INV>
__device__ __forceinline__ float2 wmulc(float2 a, float cr, float ci_fwd) {
    float ci = INV ? -ci_fwd : ci_fwd;
    return make_float2(a.x * cr - a.y * ci, a.x * ci + a.y * cr);
}

template <bool INV>
__device__ __forceinline__ void bfly4(float2 v[4]) {
    float2 t0 = cadd(v[0], v[2]);
    float2 t1 = csub(v[0], v[2]);
    float2 t2 = cadd(v[1], v[3]);
    float2 t3 = csub(v[1], v[3]);
    v[0] = cadd(t0, t2);
    v[2] = csub(t0, t2);
    if (!INV) {
        v[1] = make_float2(t1.x + t3.y, t1.y - t3.x);
        v[3] = make_float2(t1.x - t3.y, t1.y + t3.x);
    } else {
        v[1] = make_float2(t1.x - t3.y, t1.y + t3.x);
        v[3] = make_float2(t1.x + t3.y, t1.y - t3.x);
    }
}

// natural-order DFT-8 in registers (DIT even/odd split)
template <bool INV>
__device__ __forceinline__ void dft8(float2 v[8]) {
    const float R2 = 0.7071067811865476f;
    float2 e[4] = {v[0], v[2], v[4], v[6]};
    float2 o[4] = {v[1], v[3], v[5], v[7]};
    bfly4<INV>(e);
    bfly4<INV>(o);
    o[1] = wmulc<INV>(o[1],  R2, -R2);   // W8^1
    o[2] = wmulc<INV>(o[2], 0.f, -1.f);  // W8^2
    o[3] = wmulc<INV>(o[3], -R2, -R2);   // W8^3
#pragma unroll
    for (int k = 0; k < 4; ++k) {
        v[k]     = cadd(e[k], o[k]);
        v[k + 4] = csub(e[k], o[k]);
    }
}

// ---------------------------------------------------------------------------
// Warp-local FFT-256: radix 8 -> 8 -> 4 Stockham, 32 threads/row,
// 8 regs/thread, 2 smem exchanges, __syncwarp only.
// Input  v[r] = x[t + 32r];  Output v[r] = X[t + 64r], v[r+4] = X[t+32+64r].
// s0/s1: per-row padded buffers of >= 287 float2 each.
// ---------------------------------------------------------------------------
template <bool INV>
__device__ __forceinline__ void fft256_w(float2 v[8], float2* s0, float2* s1,
                                         int t, const float2* tw) {
    // stage A: Ns=1, radix-8, jm=0 (no twiddle)
    dft8<INV>(v);
#pragma unroll
    for (int r = 0; r < 8; ++r) s0[SP8(8 * t + r)] = v[r];
    __syncwarp();
    // stage B: Ns=8, radix-8, twiddle unit = 256/64 = 4
    {
        int jm = t & 7;
#pragma unroll
        for (int r = 0; r < 8; ++r) v[r] = s0[SP8(t + 32 * r)];
#pragma unroll
        for (int r = 1; r < 8; ++r) v[r] = twmul<INV>(v[r], tw[4 * jm * r]);
        dft8<INV>(v);
        int base = 8 * (t - jm) + jm;
#pragma unroll
        for (int r = 0; r < 8; ++r) s1[SP8(base + 8 * r)] = v[r];
    }
    __syncwarp();
    // stage C: Ns=64, radix-4, twiddle unit = 1; butterflies j = t, t+32
    {
        float2 a[4], b[4];
#pragma unroll
        for (int r = 0; r < 4; ++r) {
            a[r] = s1[SP8(t + 64 * r)];
            b[r] = s1[SP8(t + 32 + 64 * r)];
        }
#pragma unroll
        for (int r = 1; r < 4; ++r) {
            a[r] = twmul<INV>(a[r], tw[t * r]);
            b[r] = twmul<INV>(b[r], tw[(t + 32) * r]);
        }
        bfly4<INV>(a);
        bfly4<INV>(b);
#pragma unroll
        for (int r = 0; r < 4; ++r) { v[r] = a[r]; v[r + 4] = b[r]; }
    }
}

// ---------------------------------------------------------------------------
// N=256 radix-4 Stockham; lane = 64 threads (2 warps) -> __syncthreads.
// (still used by k_fb)
// ---------------------------------------------------------------------------
template <bool INV>
__device__ __forceinline__ void fft256_core(float2 v[4], float2* s0, float2* s1,
                                            int t, const float2* tw) {
    bfly4<INV>(v);
    s0[SP(4 * t + 0)] = v[0]; s0[SP(4 * t + 1)] = v[1];
    s0[SP(4 * t + 2)] = v[2]; s0[SP(4 * t + 3)] = v[3];
    __syncthreads();
    {
        int jm = t & 3;
        v[0] = s0[SP(t)];       v[1] = s0[SP(t + 64)];
        v[2] = s0[SP(t + 128)]; v[3] = s0[SP(t + 192)];
        v[1] = twmul<INV>(v[1], tw[16 * jm]);
        v[2] = twmul<INV>(v[2], tw[32 * jm]);
        v[3] = twmul<INV>(v[3], tw[48 * jm]);
        bfly4<INV>(v);
        int d = 4 * (t - jm) + jm;
        s1[SP(d)] = v[0]; s1[SP(d + 4)] = v[1];
        s1[SP(d + 8)] = v[2]; s1[SP(d + 12)] = v[3];
    }
    __syncthreads();
    {
        int jm = t & 15;
        v[0] = s1[SP(t)];       v[1] = s1[SP(t + 64)];
        v[2] = s1[SP(t + 128)]; v[3] = s1[SP(t + 192)];
        v[1] = twmul<INV>(v[1], tw[4 * jm]);
        v[2] = twmul<INV>(v[2], tw[8 * jm]);
        v[3] = twmul<INV>(v[3], tw[12 * jm]);
        bfly4<INV>(v);
        int d = 4 * (t - jm) + jm;
        s0[SP(d)] = v[0]; s0[SP(d + 16)] = v[1];
        s0[SP(d + 32)] = v[2]; s0[SP(d + 48)] = v[3];
    }
    __syncthreads();
    {
        v[0] = s0[SP(t)];       v[1] = s0[SP(t + 64)];
        v[2] = s0[SP(t + 128)]; v[3] = s0[SP(t + 192)];
        v[1] = twmul<INV>(v[1], tw[t]);
        v[2] = twmul<INV>(v[2], tw[2 * t]);
        v[3] = twmul<INV>(v[3], tw[3 * t]);
        bfly4<INV>(v);
    }
}

// ---------------------------------------------------------------------------
// N=128 radix-4x3 + radix-2; lane = exactly one warp -> __syncwarp only.
// ---------------------------------------------------------------------------
template <bool INV>
__device__ __forceinline__ void fft128_core(float2 v[4], float2* s0, float2* s1,
                                            int t, const float2* tw) {
    bfly4<INV>(v);
    s0[SP(4 * t + 0)] = v[0]; s0[SP(4 * t + 1)] = v[1];
    s0[SP(4 * t + 2)] = v[2]; s0[SP(4 * t + 3)] = v[3];
    __syncwarp();
    {
        int jm = t & 3;
        v[0] = s0[SP(t)];      v[1] = s0[SP(t + 32)];
        v[2] = s0[SP(t + 64)]; v[3] = s0[SP(t + 96)];
        v[1] = twmul<INV>(v[1], tw[16 * jm]);
        v[2] = twmul<INV>(v[2], tw[32 * jm]);
        v[3] = twmul<INV>(v[3], tw[48 * jm]);
        bfly4<INV>(v);
        int d = 4 * (t - jm) + jm;
        s1[SP(d)] = v[0]; s1[SP(d + 4)] = v[1];
        s1[SP(d + 8)] = v[2]; s1[SP(d + 12)] = v[3];
    }
    __syncwarp();
    {
        int jm = t & 15;
        v[0] = s1[SP(t)];      v[1] = s1[SP(t + 32)];
        v[2] = s1[SP(t + 64)]; v[3] = s1[SP(t + 96)];
        v[1] = twmul<INV>(v[1], tw[4 * jm]);
        v[2] = twmul<INV>(v[2], tw[8 * jm]);
        v[3] = twmul<INV>(v[3], tw[12 * jm]);
        bfly4<INV>(v);
        int d = 4 * (t - jm) + jm;
        s0[SP(d)] = v[0]; s0[SP(d + 16)] = v[1];
        s0[SP(d + 32)] = v[2]; s0[SP(d + 48)] = v[3];
    }
    __syncwarp();
    {
        float2 a0 = s0[SP(t)],      b0 = s0[SP(t + 64)];
        float2 a1 = s0[SP(t + 32)], b1 = s0[SP(t + 96)];
        float2 bw0 = twmul<INV>(b0, tw[2 * t]);
        float2 bw1 = twmul<INV>(b1, tw[2 * (t + 32)]);
        v[0] = cadd(a0, bw0);
        v[2] = csub(a0, bw0);
        v[1] = cadd(a1, bw1);
        v[3] = csub(a1, bw1);
    }
}

// ---------------------------------------------------------------------------
// FUSED FB: per-plane. Phase 1: 25 row FFTs (N=256) of rolled PSF rows into
// smem Rf. Phase 2: 25-term direct column DFT -> FB^T rows 0..128 (Hermitian).
// ---------------------------------------------------------------------------
__global__ void __launch_bounds__(512, 2)
k_fb(const float* __restrict__ psf, float2* __restrict__ FBt) {
    __shared__ float2 Rf[25][256];
    __shared__ float2 sbuf[8][2 * 272];
    __shared__ float2 stw[256];
    int t = threadIdx.x;      // 0..63
    int g = threadIdx.y;      // 0..7
    int tid = g * 64 + t;
    if (tid < 256) stw[tid] = twval(tid);
    __syncthreads();

    int p = blockIdx.x;
#pragma unroll
    for (int it = 0; it < 4; ++it) {
        int r = g + 8 * it;
        int rr = r < 25 ? r : 24;
        const float* kp = psf + p * 625 + rr * 25;
        float2 v[4];
#pragma unroll
        for (int q = 0; q < 4; ++q) {
            int c = (t + 64 * q + 12) & 255;
            v[q] = make_float2(c < 25 ? kp[c] : 0.f, 0.f);
        }
        fft256_core<false>(v, sbuf[g], sbuf[g] + 272, t, stw);
        if (r < 25) {
            Rf[r][t] = v[0]; Rf[r][t + 64] = v[1];
            Rf[r][t + 128] = v[2]; Rf[r][t + 192] = v[3];
        }
    }
    __syncthreads();

    int v = tid & 255;
    int uc = tid >> 8;
    float2 twr[25];
#pragma unroll
    for (int r = 0; r < 25; ++r)
        twr[r] = stw[(v * (r - 12)) & 255];
    float2* Fp = FBt + p * HSTRIDE;
    for (int u = uc; u <= 128; u += 2) {
        float2 acc = make_float2(0.f, 0.f);
#pragma unroll
        for (int r = 0; r < 25; ++r) {
            float2 a = Rf[r][u];
            acc.x += a.x * twr[r].x - a.y * twr[r].y;
            acc.y += a.x * twr[r].y + a.y * twr[r].x;
        }
        Fp[u * 256 + v] = acc;
    }
}

// ---------------------------------------------------------------------------
// FUSED per-plane 2D FFT of x -> Fx^T[p][u][vh] (XOR-swizzled smem tile).
// ---------------------------------------------------------------------------
__global__ void __launch_bounds__(1024, 1)
k_xfft2(const float* __restrict__ x, float2* __restrict__ Fx) {
    extern __shared__ float2 tile[];          // 128*128 float2 = 128KB dynamic
    __shared__ float2 sbuf[32][2 * 136];
    __shared__ float2 stw[256];
    int t = threadIdx.x;                      // 0..31
    int w = threadIdx.y;                      // 0..31
    int tid = w * 32 + t;
    if (tid < 256) stw[tid] = twval(tid);
    __syncthreads();

    int p = blockIdx.x;
    const float* xp = x + p * 16384;

#pragma unroll
    for (int it = 0; it < 2; ++it) {
        int j = w + 32 * it;
        const float* xa = xp + j * 256;
        float2 v[4];
#pragma unroll
        for (int q = 0; q < 4; ++q)
            v[q] = make_float2(xa[t + 32 * q], xa[128 + t + 32 * q]);
        fft128_core<false>(v, sbuf[w], sbuf[w] + 136, t, stw);
        float2* s0 = sbuf[w];
#pragma unroll
        for (int q = 0; q < 4; ++q) s0[SP(t + 32 * q)] = v[q];
        __syncwarp();
        int ya = 2 * j, yb = 2 * j + 1;
        int sa = ya & 31, sb = yb & 31;
#pragma unroll
        for (int q = 0; q < 4; ++q) {
            int k = t + 32 * q;
            float2 Zk = s0[SP(k)];
            float2 Zm = s0[SP((128 - k) & 127)];
            tile[ya * 128 + (k ^ sa)] =
                make_float2(0.5f * (Zk.x + Zm.x), 0.5f * (Zk.y - Zm.y));
            tile[yb * 128 + (k ^ sb)] =
                make_float2(0.5f * (Zk.y + Zm.y), 0.5f * (Zm.x - Zk.x));
        }
        __syncwarp();
    }
    __syncthreads();

    float2* Fp = Fx + p * 16384;
#pragma unroll
    for (int rep = 0; rep < 4; ++rep) {
        int u = w + 32 * rep;
        float2 v[4];
#pragma unroll
        for (int q = 0; q < 4; ++q) {
            int y = t + 32 * q;
            v[q] = tile[y * 128 + (u ^ (y & 31))];
        }
        fft128_core<false>(v, sbuf[w], sbuf[w] + 136, t, stw);
        float2* d = Fp + u * 128;
        d[t] = v[0]; d[t + 32] = v[1]; d[t + 64] = v[2]; d[t + 96] = v[3];
    }
}

// ---------------------------------------------------------------------------
// FUSED solve + inverse-256: one spectrum row A per WARP (32 lanes, 8 regs),
// radix 8-8-4 warp-local FFT. Block (32,8) = 8 rows, no block syncs in loop.
// ---------------------------------------------------------------------------
__global__ void __launch_bounds__(256)
k_solve(const float* __restrict__ alpha) {
    __shared__ float2 sA[8][288];
    __shared__ float2 sB[8][288];
    __shared__ float2 stw[256];
    int t = threadIdx.x;       // 0..31
    int ry = threadIdx.y;      // 0..7
    int tid = ry * 32 + t;
    stw[tid] = twval(tid);
    __syncthreads();

    int p = blockIdx.y;
    int A = blockIdx.x * 8 + ry;               // 0..135; rows >128 idle-write
    int AA = A <= 128 ? A : 128;
    bool hi = (AA == 128);
    int vv = hi ? 0 : AA;

    float a = alpha[p & (NCH - 1)];
    float be = 1.f / (1.f + expf(9.f - a)) + 1e-3f;
    float ibe = 1.f / be;

    const float2* FBp = g_SA + p * HSTRIDE;
    const float2* FBd = FBp + vv * 256;
    const float2* FBm = FBp + (128 - vv) * 256;
    const float2* Fxr = g_SC + (p << 14) + (vv << 7);

    float2 twv0 = stw[vv], twv1 = stw[vv + 128];
    float2 pv0 = make_float2(1.f + twv0.x, twv0.y);
    float2 pv1 = make_float2(1.f + twv1.x, twv1.y);

    float2 v[8];
#pragma unroll
    for (int q = 0; q < 4; ++q) {
        int u = t + 32 * q;                    // < 128
        float2 fx = Fxr[u];

        float2 FB[4];
        FB[0] = FBd[u];
        FB[1] = FBd[u + 128];
        if (vv == 0) {
            FB[2] = FBm[u];
            FB[3] = FBm[u + 128];
        } else {
            float2 t0 = FBm[(256 - u) & 255];
            float2 t1 = FBm[128 - u];
            FB[2] = make_float2(t0.x, -t0.y);
            FB[3] = make_float2(t1.x, -t1.y);
        }

        float2 twu0 = stw[u], twu1 = stw[u + 128];
        float2 pu0 = make_float2(1.f + twu0.x, twu0.y);
        float2 pu1 = make_float2(1.f + twu1.x, twu1.y);

        float2 FR[4];
        float2 sBR = make_float2(0.f, 0.f);
        float sW = 0.f;
#pragma unroll
        for (int q2 = 0; q2 < 4; ++q2) {
            float2 fb = FB[q2];
            float2 P = cmulf((q2 & 1) ? pu1 : pu0, (q2 >> 1) ? pv1 : pv0);
            float2 m = make_float2(fb.x + be * P.x, -fb.y + be * P.y);
            float2 fr = cmulf(fx, m);
            FR[q2] = fr;
            sBR.x += fb.x * fr.x - fb.y * fr.y;
            sBR.y += fb.x * fr.y + fb.y * fr.x;
            sW += fb.x * fb.x + fb.y * fb.y;
        }
        sBR.x *= 0.25f; sBR.y *= 0.25f; sW *= 0.25f;
        float inv = 1.f / (sW + be);
        float2 iw = make_float2(sBR.x * inv, sBR.y * inv);

        int qlo = hi ? 2 : 0;
#pragma unroll
        for (int j = 0; j < 2; ++j) {
            int qq = qlo + j;
            float2 tmp = make_float2(FB[qq].x * iw.x + FB[qq].y * iw.y,
                                     FB[qq].x * iw.y - FB[qq].y * iw.x);
            float2 Q = make_float2((FR[qq].x - tmp.x) * ibe,
                                   (FR[qq].y - tmp.y) * ibe);
            v[q + 4 * j] = Q;    // FX[t+32q] and FX[t+32q+128] = FX[t+32(q+4)]
        }
    }

    fft256_w<true>(v, sA[ry], sB[ry], t, stw);

    if (A <= 128) {
        float2* d = g_SB + p * HSTRIDE + A * 256;
#pragma unroll
        for (int r = 0; r < 4; ++r) {
            d[t + 64 * r]      = v[r];
            d[t + 32 + 64 * r] = v[r + 4];
        }
    }
}

// ---------------------------------------------------------------------------
// Final: fused transpose + Hermitian-packed real inverse along width.
// ---------------------------------------------------------------------------
__global__ void k_final(const float2* __restrict__ G, float2* __restrict__ out2) {
    __shared__ float2 tile[129][17];
    __shared__ float2 sbuf[8][2 * 136];
    __shared__ float2 stw[256];
    int t = threadIdx.x, f = threadIdx.y;      // (32,8)
    int tid = f * 32 + t;
    stw[tid] = twval(tid);
    int p = blockIdx.y, x0 = blockIdx.x * 16;
    const float2* Gp = G + p * HSTRIDE;
#pragma unroll
    for (int it = 0; it < 9; ++it) {
        int idx = it * 256 + tid;
        int A = idx >> 4, ff = idx & 15;
        if (A < 129) tile[A][ff] = Gp[A * 256 + x0 + ff];
    }
    __syncthreads();
    const float s = 1.0f / 65536.0f;
#pragma unroll
    for (int rep = 0; rep < 2; ++rep) {
        int fc = f + 8 * rep;
        float2 v[4];
#pragma unroll
        for (int q = 0; q < 4; ++q) {
            int k = t + 32 * q;
            float2 hk = tile[k][fc];
            float2 hm = tile[128 - k][fc];
            float2 c = stw[k];
            float Ax = hk.x + hm.x, Ay = hk.y - hm.y;
            float Bx = hk.x - hm.x, By = hk.y + hm.y;
            float cr = c.x * Bx + c.y * By;
            float ci = c.x * By - c.y * Bx;
            v[q] = make_float2(Ax - ci, Ay + cr);
        }
        fft128_core<true>(v, sbuf[f], sbuf[f] + 136, t, stw);
        float2* d = out2 + ((p << 8) + x0 + fc) * 128;
#pragma unroll
        for (int q = 0; q < 4; ++q)
            d[t + 32 * q] = make_float2(v[q].x * s, v[q].y * s);
    }
}

extern "C" void kernel_launch(void* const* d_in, const int* in_sizes, int n_in,
                              void* d_out, int out_size) {
    const float* x     = (const float*)d_in[0];
    const float* psf   = (const float*)d_in[1];
    const float* alpha = (const float*)d_in[2];
    float* out = (float*)d_out;

    float2 *SA, *SB, *SC;
    cudaGetSymbolAddress((void**)&SA, g_SA);
    cudaGetSymbolAddress((void**)&SB, g_SB);
    cudaGetSymbolAddress((void**)&SC, g_SC);

    // 1) FB^T half (rows 0..128) -> SA
    k_fb<<<NPLANES, dim3(64, 8)>>>(psf, SA);

    // 2) Fx^T[p][u][vh] -> SC
    cudaFuncSetAttribute(k_xfft2, cudaFuncAttributeMaxDynamicSharedMemorySize,
                         128 * 128 * sizeof(float2));
    k_xfft2<<<NPLANES, dim3(32, 32), 128 * 128 * sizeof(float2)>>>(x, SC);

    // 3) FUSED solve + warp-local inverse-256 -> SB holds G half
    k_solve<<<dim3(17, NPLANES), dim3(32, 8)>>>(alpha);

    // 4) Hermitian-packed real inverse along width -> out
    k_final<<<dim3(16, NPLANES), dim3(32, 8)>>>(SB, (float2*)out);
}

// round 14
// speedup vs baseline: 1.3074x; 1.3074x over previous
#include <cuda_runtime.h>
#include <math.h>

// Shapes fixed: x (4,64,128,128), k (4,64,25,25), alpha (1,64,1,1), sf=2.
// Output (4,64,256,256) fp32.
#define NPLANES 256
#define NCH 64
#define HSTRIDE (129 * 256)   // half-spectrum plane stride (rows 0..128)

__device__ float2 g_SA[NPLANES * HSTRIDE];     // FB half
__device__ float2 g_SB[NPLANES * HSTRIDE];     // G half
__device__ float2 g_SC[NPLANES * 128 * 128];   // Fx^T

#define SP(i) ((i) + ((i) >> 4))

// in-kernel twiddle: e^{-2 pi i t/256}
__device__ __forceinline__ float2 twval(int t) {
    float s, c;
    sincospif(-(float)t * (1.0f / 128.0f), &s, &c);
    return make_float2(c, s);
}

__device__ __forceinline__ float2 cmulf(float2 a, float2 b) {
    return make_float2(a.x * b.x - a.y * b.y, a.x * b.y + a.y * b.x);
}

template <bool INV>
__device__ __forceinline__ float2 twmul(float2 a, float2 w) {
    float wy = INV ? -w.y : w.y;
    return make_float2(a.x * w.x - a.y * wy, a.x * wy + a.y * w.x);
}

template <bool INV>
__device__ __forceinline__ void bfly4(float2 v[4]) {
    float2 t0 = make_float2(v[0].x + v[2].x, v[0].y + v[2].y);
    float2 t1 = make_float2(v[0].x - v[2].x, v[0].y - v[2].y);
    float2 t2 = make_float2(v[1].x + v[3].x, v[1].y + v[3].y);
    float2 t3 = make_float2(v[1].x - v[3].x, v[1].y - v[3].y);
    v[0] = make_float2(t0.x + t2.x, t0.y + t2.y);
    v[2] = make_float2(t0.x - t2.x, t0.y - t2.y);
    if (!INV) {
        v[1] = make_float2(t1.x + t3.y, t1.y - t3.x);
        v[3] = make_float2(t1.x - t3.y, t1.y + t3.x);
    } else {
        v[1] = make_float2(t1.x - t3.y, t1.y + t3.x);
        v[3] = make_float2(t1.x + t3.y, t1.y - t3.x);
    }
}

// ---------------------------------------------------------------------------
// N=256 radix-4 Stockham; lane = 64 threads (2 warps) -> __syncthreads.
// Trailing __syncthreads makes back-to-back calls on the same buffers safe
// (stage-4 reads must complete before the next call's stage-1 writes).
// ---------------------------------------------------------------------------
template <bool INV>
__device__ __forceinline__ void fft256_core(float2 v[4], float2* s0, float2* s1,
                                            int t, const float2* tw) {
    bfly4<INV>(v);
    s0[SP(4 * t + 0)] = v[0]; s0[SP(4 * t + 1)] = v[1];
    s0[SP(4 * t + 2)] = v[2]; s0[SP(4 * t + 3)] = v[3];
    __syncthreads();
    {
        int jm = t & 3;
        v[0] = s0[SP(t)];       v[1] = s0[SP(t + 64)];
        v[2] = s0[SP(t + 128)]; v[3] = s0[SP(t + 192)];
        v[1] = twmul<INV>(v[1], tw[16 * jm]);
        v[2] = twmul<INV>(v[2], tw[32 * jm]);
        v[3] = twmul<INV>(v[3], tw[48 * jm]);
        bfly4<INV>(v);
        int d = 4 * (t - jm) + jm;
        s1[SP(d)] = v[0]; s1[SP(d + 4)] = v[1];
        s1[SP(d + 8)] = v[2]; s1[SP(d + 12)] = v[3];
    }
    __syncthreads();
    {
        int jm = t & 15;
        v[0] = s1[SP(t)];       v[1] = s1[SP(t + 64)];
        v[2] = s1[SP(t + 128)]; v[3] = s1[SP(t + 192)];
        v[1] = twmul<INV>(v[1], tw[4 * jm]);
        v[2] = twmul<INV>(v[2], tw[8 * jm]);
        v[3] = twmul<INV>(v[3], tw[12 * jm]);
        bfly4<INV>(v);
        int d = 4 * (t - jm) + jm;
        s0[SP(d)] = v[0]; s0[SP(d + 16)] = v[1];
        s0[SP(d + 32)] = v[2]; s0[SP(d + 48)] = v[3];
    }
    __syncthreads();
    {
        v[0] = s0[SP(t)];       v[1] = s0[SP(t + 64)];
        v[2] = s0[SP(t + 128)]; v[3] = s0[SP(t + 192)];
        v[1] = twmul<INV>(v[1], tw[t]);
        v[2] = twmul<INV>(v[2], tw[2 * t]);
        v[3] = twmul<INV>(v[3], tw[3 * t]);
        bfly4<INV>(v);
    }
    __syncthreads();   // RACE FIX: protect s0 reads from next call's writes
}

// ---------------------------------------------------------------------------
// N=128 radix-4x3 + radix-2; lane = exactly one warp -> __syncwarp only.
// Trailing __syncwarp protects the final-stage reads (ITS safety for loops).
// ---------------------------------------------------------------------------
template <bool INV>
__device__ __forceinline__ void fft128_core(float2 v[4], float2* s0, float2* s1,
                                            int t, const float2* tw) {
    bfly4<INV>(v);
    s0[SP(4 * t + 0)] = v[0]; s0[SP(4 * t + 1)] = v[1];
    s0[SP(4 * t + 2)] = v[2]; s0[SP(4 * t + 3)] = v[3];
    __syncwarp();
    {
        int jm = t & 3;
        v[0] = s0[SP(t)];      v[1] = s0[SP(t + 32)];
        v[2] = s0[SP(t + 64)]; v[3] = s0[SP(t + 96)];
        v[1] = twmul<INV>(v[1], tw[16 * jm]);
        v[2] = twmul<INV>(v[2], tw[32 * jm]);
        v[3] = twmul<INV>(v[3], tw[48 * jm]);
        bfly4<INV>(v);
        int d = 4 * (t - jm) + jm;
        s1[SP(d)] = v[0]; s1[SP(d + 4)] = v[1];
        s1[SP(d + 8)] = v[2]; s1[SP(d + 12)] = v[3];
    }
    __syncwarp();
    {
        int jm = t & 15;
        v[0] = s1[SP(t)];      v[1] = s1[SP(t + 32)];
        v[2] = s1[SP(t + 64)]; v[3] = s1[SP(t + 96)];
        v[1] = twmul<INV>(v[1], tw[4 * jm]);
        v[2] = twmul<INV>(v[2], tw[8 * jm]);
        v[3] = twmul<INV>(v[3], tw[12 * jm]);
        bfly4<INV>(v);
        int d = 4 * (t - jm) + jm;
        s0[SP(d)] = v[0]; s0[SP(d + 16)] = v[1];
        s0[SP(d + 32)] = v[2]; s0[SP(d + 48)] = v[3];
    }
    __syncwarp();
    {
        float2 a0 = s0[SP(t)],      b0 = s0[SP(t + 64)];
        float2 a1 = s0[SP(t + 32)], b1 = s0[SP(t + 96)];
        float2 bw0 = twmul<INV>(b0, tw[2 * t]);
        float2 bw1 = twmul<INV>(b1, tw[2 * (t + 32)]);
        v[0] = make_float2(a0.x + bw0.x, a0.y + bw0.y);
        v[2] = make_float2(a0.x - bw0.x, a0.y - bw0.y);
        v[1] = make_float2(a1.x + bw1.x, a1.y + bw1.y);
        v[3] = make_float2(a1.x - bw1.x, a1.y - bw1.y);
    }
    __syncwarp();      // RACE FIX: protect s0 reads from next call's writes
}

// ---------------------------------------------------------------------------
// FUSED FB: per-plane. Phase 1: 25 row FFTs (N=256) of rolled PSF rows into
// smem Rf. Phase 2: 25-term direct column DFT -> FB^T rows 0..128 (Hermitian).
// ---------------------------------------------------------------------------
__global__ void __launch_bounds__(512, 2)
k_fb(const float* __restrict__ psf, float2* __restrict__ FBt) {
    __shared__ float2 Rf[25][256];
    __shared__ float2 sbuf[8][2 * 272];
    __shared__ float2 stw[256];
    int t = threadIdx.x;      // 0..63
    int g = threadIdx.y;      // 0..7
    int tid = g * 64 + t;
    if (tid < 256) stw[tid] = twval(tid);
    __syncthreads();

    int p = blockIdx.x;
#pragma unroll
    for (int it = 0; it < 4; ++it) {
        int r = g + 8 * it;
        int rr = r < 25 ? r : 24;
        const float* kp = psf + p * 625 + rr * 25;
        float2 v[4];
#pragma unroll
        for (int q = 0; q < 4; ++q) {
            int c = (t + 64 * q + 12) & 255;
            v[q] = make_float2(c < 25 ? kp[c] : 0.f, 0.f);
        }
        fft256_core<false>(v, sbuf[g], sbuf[g] + 272, t, stw);
        if (r < 25) {
            Rf[r][t] = v[0]; Rf[r][t + 64] = v[1];
            Rf[r][t + 128] = v[2]; Rf[r][t + 192] = v[3];
        }
    }
    __syncthreads();

    int v = tid & 255;
    int uc = tid >> 8;
    float2 twr[25];
#pragma unroll
    for (int r = 0; r < 25; ++r)
        twr[r] = stw[(v * (r - 12)) & 255];
    float2* Fp = FBt + p * HSTRIDE;
    for (int u = uc; u <= 128; u += 2) {
        float2 acc = make_float2(0.f, 0.f);
#pragma unroll
        for (int r = 0; r < 25; ++r) {
            float2 a = Rf[r][u];
            acc.x += a.x * twr[r].x - a.y * twr[r].y;
            acc.y += a.x * twr[r].y + a.y * twr[r].x;
        }
        Fp[u * 256 + v] = acc;
    }
}

// ---------------------------------------------------------------------------
// FUSED per-plane 2D FFT of x -> Fx^T[p][u][vh] (XOR-swizzled smem tile).
// ---------------------------------------------------------------------------
__global__ void __launch_bounds__(1024, 1)
k_xfft2(const float* __restrict__ x, float2* __restrict__ Fx) {
    extern __shared__ float2 tile[];          // 128*128 float2 = 128KB dynamic
    __shared__ float2 sbuf[32][2 * 136];
    __shared__ float2 stw[256];
    int t = threadIdx.x;                      // 0..31
    int w = threadIdx.y;                      // 0..31
    int tid = w * 32 + t;
    if (tid < 256) stw[tid] = twval(tid);
    __syncthreads();

    int p = blockIdx.x;
    const float* xp = x + p * 16384;

#pragma unroll
    for (int it = 0; it < 2; ++it) {
        int j = w + 32 * it;
        const float* xa = xp + j * 256;
        float2 v[4];
#pragma unroll
        for (int q = 0; q < 4; ++q)
            v[q] = make_float2(xa[t + 32 * q], xa[128 + t + 32 * q]);
        fft128_core<false>(v, sbuf[w], sbuf[w] + 136, t, stw);
        float2* s0 = sbuf[w];
#pragma unroll
        for (int q = 0; q < 4; ++q) s0[SP(t + 32 * q)] = v[q];
        __syncwarp();
        int ya = 2 * j, yb = 2 * j + 1;
        int sa = ya & 31, sb = yb & 31;
#pragma unroll
        for (int q = 0; q < 4; ++q) {
            int k = t + 32 * q;
            float2 Zk = s0[SP(k)];
            float2 Zm = s0[SP((128 - k) & 127)];
            tile[ya * 128 + (k ^ sa)] =
                make_float2(0.5f * (Zk.x + Zm.x), 0.5f * (Zk.y - Zm.y));
            tile[yb * 128 + (k ^ sb)] =
                make_float2(0.5f * (Zk.y + Zm.y), 0.5f * (Zm.x - Zk.x));
        }
        __syncwarp();
    }
    __syncthreads();

    float2* Fp = Fx + p * 16384;
#pragma unroll
    for (int rep = 0; rep < 4; ++rep) {
        int u = w + 32 * rep;
        float2 v[4];
#pragma unroll
        for (int q = 0; q < 4; ++q) {
            int y = t + 32 * q;
            v[q] = tile[y * 128 + (u ^ (y & 31))];
        }
        fft128_core<false>(v, sbuf[w], sbuf[w] + 136, t, stw);
        float2* d = Fp + u * 128;
        d[t] = v[0]; d[t + 32] = v[1]; d[t + 64] = v[2]; d[t + 96] = v[3];
    }
}

// ---------------------------------------------------------------------------
// FUSED solve + inverse-256, CANCELLATION-FREE closed form:
//   S = mean_q(FB_q P_q),  W = mean_q|FB_q|^2
//   FX_q = Fx * ( P_q + conj(FB_q) * (1-S)/(W+be) )
// (the /be of the reference cancels analytically -> no error amplification)
// ---------------------------------------------------------------------------
__global__ void k_solve(const float* __restrict__ alpha) {
    __shared__ float2 sbuf[8][2 * 272];
    __shared__ float2 stw[256];
    int t = threadIdx.x, ry = threadIdx.y;     // (64,8)
    int lt = ry * 64 + t;
    if (lt < 256) stw[lt] = twval(lt);
    __syncthreads();

    int p = blockIdx.y;
    int A = blockIdx.x * 8 + ry;               // 0..135; rows >128 idle-write
    int AA = A <= 128 ? A : 128;
    bool hi = (AA == 128);
    int vv = hi ? 0 : AA;

    float a = alpha[p & (NCH - 1)];
    float be = 1.f / (1.f + expf(9.f - a)) + 1e-3f;

    const float2* FBp = g_SA + p * HSTRIDE;
    const float2* FBd = FBp + vv * 256;
    const float2* FBm = FBp + (128 - vv) * 256;
    const float2* Fxr = g_SC + (p << 14) + (vv << 7);

    float2 twv0 = stw[vv], twv1 = stw[vv + 128];
    float2 pv0 = make_float2(1.f + twv0.x, twv0.y);
    float2 pv1 = make_float2(1.f + twv1.x, twv1.y);

    float2 v[4];
#pragma unroll
    for (int half = 0; half < 2; ++half) {
        int u = t + 64 * half;
        float2 fx = Fxr[u];

        float2 FB[4];
        FB[0] = FBd[u];
        FB[1] = FBd[u + 128];
        if (vv == 0) {
            FB[2] = FBm[u];
            FB[3] = FBm[u + 128];
        } else {
            float2 t0 = FBm[(256 - u) & 255];
            float2 t1 = FBm[128 - u];
            FB[2] = make_float2(t0.x, -t0.y);
            FB[3] = make_float2(t1.x, -t1.y);
        }

        float2 twu0 = stw[u], twu1 = stw[u + 128];
        float2 pu0 = make_float2(1.f + twu0.x, twu0.y);
        float2 pu1 = make_float2(1.f + twu1.x, twu1.y);

        float2 P[4];
        P[0] = cmulf(pu0, pv0);
        P[1] = cmulf(pu1, pv0);
        P[2] = cmulf(pu0, pv1);
        P[3] = cmulf(pu1, pv1);

        float2 S = make_float2(0.f, 0.f);
        float W = 0.f;
#pragma unroll
        for (int q = 0; q < 4; ++q) {
            float2 fb = FB[q];
            S.x += fb.x * P[q].x - fb.y * P[q].y;
            S.y += fb.x * P[q].y + fb.y * P[q].x;
            W += fb.x * fb.x + fb.y * fb.y;
        }
        S.x *= 0.25f; S.y *= 0.25f; W *= 0.25f;
        float inv = 1.f / (W + be);
        float2 c = make_float2((1.f - S.x) * inv, -S.y * inv);

        int qlo = hi ? 2 : 0;
#pragma unroll
        for (int j = 0; j < 2; ++j) {
            int q = qlo + j;
            // m = P_q + conj(FB_q)*c
            float2 m = make_float2(
                P[q].x + FB[q].x * c.x + FB[q].y * c.y,
                P[q].y + FB[q].x * c.y - FB[q].y * c.x);
            v[half + 2 * j] = cmulf(fx, m);
        }
    }

    fft256_core<true>(v, sbuf[ry], sbuf[ry] + 272, t, stw);

    if (A <= 128) {
        float2* d = g_SB + p * HSTRIDE + A * 256;
        d[t] = v[0]; d[t + 64] = v[1]; d[t + 128] = v[2]; d[t + 192] = v[3];
    }
}

// ---------------------------------------------------------------------------
// Final: fused transpose + Hermitian-packed real inverse along width.
// ---------------------------------------------------------------------------
__global__ void k_final(const float2* __restrict__ G, float2* __restrict__ out2) {
    __shared__ float2 tile[129][17];
    __shared__ float2 sbuf[8][2 * 136];
    __shared__ float2 stw[256];
    int t = threadIdx.x, f = threadIdx.y;      // (32,8)
    int tid = f * 32 + t;
    stw[tid] = twval(tid);
    int p = blockIdx.y, x0 = blockIdx.x * 16;
    const float2* Gp = G + p * HSTRIDE;
#pragma unroll
    for (int it = 0; it < 9; ++it) {
        int idx = it * 256 + tid;
        int A = idx >> 4, ff = idx & 15;
        if (A < 129) tile[A][ff] = Gp[A * 256 + x0 + ff];
    }
    __syncthreads();
    const float s = 1.0f / 65536.0f;
#pragma unroll
    for (int rep = 0; rep < 2; ++rep) {
        int fc = f + 8 * rep;
        float2 v[4];
#pragma unroll
        for (int q = 0; q < 4; ++q) {
            int k = t + 32 * q;
            float2 hk = tile[k][fc];
            float2 hm = tile[128 - k][fc];
            float2 c = stw[k];
            float Ax = hk.x + hm.x, Ay = hk.y - hm.y;
            float Bx = hk.x - hm.x, By = hk.y + hm.y;
            float cr = c.x * Bx + c.y * By;
            float ci = c.x * By - c.y * Bx;
            v[q] = make_float2(Ax - ci, Ay + cr);
        }
        fft128_core<true>(v, sbuf[f], sbuf[f] + 136, t, stw);
        float2* d = out2 + ((p << 8) + x0 + fc) * 128;
#pragma unroll
        for (int q = 0; q < 4; ++q)
            d[t + 32 * q] = make_float2(v[q].x * s, v[q].y * s);
    }
}

extern "C" void kernel_launch(void* const* d_in, const int* in_sizes, int n_in,
                              void* d_out, int out_size) {
    const float* x     = (const float*)d_in[0];
    const float* psf   = (const float*)d_in[1];
    const float* alpha = (const float*)d_in[2];
    float* out = (float*)d_out;

    float2 *SA, *SB, *SC;
    cudaGetSymbolAddress((void**)&SA, g_SA);
    cudaGetSymbolAddress((void**)&SB, g_SB);
    cudaGetSymbolAddress((void**)&SC, g_SC);

    // 1) FB^T half (rows 0..128) -> SA
    k_fb<<<NPLANES, dim3(64, 8)>>>(psf, SA);

    // 2) Fx^T[p][u][vh] -> SC
    cudaFuncSetAttribute(k_xfft2, cudaFuncAttributeMaxDynamicSharedMemorySize,
                         128 * 128 * sizeof(float2));
    k_xfft2<<<NPLANES, dim3(32, 32), 128 * 128 * sizeof(float2)>>>(x, SC);

    // 3) Cancellation-free solve + inverse-256 -> SB holds G half
    k_solve<<<dim3(17, NPLANES), dim3(64, 8)>>>(alpha);

    // 4) Hermitian-packed real inverse along width -> out
    k_final<<<dim3(16, NPLANES), dim3(32, 8)>>>(SB, (float2*)out);
}

// round 15
// speedup vs baseline: 1.4299x; 1.0937x over previous
#include <cuda_runtime.h>
#include <math.h>

// Shapes fixed: x (4,64,128,128), k (4,64,25,25), alpha (1,64,1,1), sf=2.
// Output (4,64,256,256) fp32.
#define NPLANES 256
#define NCH 64
#define HSTRIDE (129 * 256)   // half-spectrum plane stride (rows 0..128)

__device__ float2 g_SA[NPLANES * HSTRIDE];     // FB half
__device__ float2 g_SB[NPLANES * HSTRIDE];     // G half
__device__ float2 g_SC[NPLANES * 128 * 128];   // Fx^T

#define SP(i) ((i) + ((i) >> 4))
#define SP8(i) ((i) + ((i) >> 3))

// in-kernel twiddle: e^{-2 pi i t/256}
__device__ __forceinline__ float2 twval(int t) {
    float s, c;
    sincospif(-(float)t * (1.0f / 128.0f), &s, &c);
    return make_float2(c, s);
}

__device__ __forceinline__ float2 cmulf(float2 a, float2 b) {
    return make_float2(a.x * b.x - a.y * b.y, a.x * b.y + a.y * b.x);
}
__device__ __forceinline__ float2 cadd(float2 a, float2 b) {
    return make_float2(a.x + b.x, a.y + b.y);
}
__device__ __forceinline__ float2 csub(float2 a, float2 b) {
    return make_float2(a.x - b.x, a.y - b.y);
}

template <bool INV>
__device__ __forceinline__ float2 twmul(float2 a, float2 w) {
    float wy = INV ? -w.y : w.y;
    return make_float2(a.x * w.x - a.y * wy, a.x * wy + a.y * w.x);
}

// complex mul by compile-time constant (forward sign); conj for INV
template <bool INV>
__device__ __forceinline__ float2 wmulc(float2 a, float cr, float ci_fwd) {
    float ci = INV ? -ci_fwd : ci_fwd;
    return make_float2(a.x * cr - a.y * ci, a.x * ci + a.y * cr);
}

template <bool INV>
__device__ __forceinline__ void bfly4(float2 v[4]) {
    float2 t0 = cadd(v[0], v[2]);
    float2 t1 = csub(v[0], v[2]);
    float2 t2 = cadd(v[1], v[3]);
    float2 t3 = csub(v[1], v[3]);
    v[0] = cadd(t0, t2);
    v[2] = csub(t0, t2);
    if (!INV) {
        v[1] = make_float2(t1.x + t3.y, t1.y - t3.x);
        v[3] = make_float2(t1.x - t3.y, t1.y + t3.x);
    } else {
        v[1] = make_float2(t1.x - t3.y, t1.y + t3.x);
        v[3] = make_float2(t1.x + t3.y, t1.y - t3.x);
    }
}

// natural-order DFT-8 in registers (DIT even/odd split)
template <bool INV>
__device__ __forceinline__ void dft8(float2 v[8]) {
    const float R2 = 0.7071067811865476f;
    float2 e[4] = {v[0], v[2], v[4], v[6]};
    float2 o[4] = {v[1], v[3], v[5], v[7]};
    bfly4<INV>(e);
    bfly4<INV>(o);
    o[1] = wmulc<INV>(o[1],  R2, -R2);   // W8^1
    o[2] = wmulc<INV>(o[2], 0.f, -1.f);  // W8^2
    o[3] = wmulc<INV>(o[3], -R2, -R2);   // W8^3
#pragma unroll
    for (int k = 0; k < 4; ++k) {
        v[k]     = cadd(e[k], o[k]);
        v[k + 4] = csub(e[k], o[k]);
    }
}

// ---------------------------------------------------------------------------
// Warp-local FFT-256: radix 8 -> 8 -> 4 Stockham, 32 threads/row,
// 8 regs/thread, 2 smem exchanges, __syncwarp only. Single call per kernel.
// Input  v[r] = x[t + 32r];  Output v[r] = X[t + 64r], v[r+4] = X[t+32+64r].
// ---------------------------------------------------------------------------
template <bool INV>
__device__ __forceinline__ void fft256_w(float2 v[8], float2* s0, float2* s1,
                                         int t, const float2* tw) {
    dft8<INV>(v);                              // stage A: Ns=1
#pragma unroll
    for (int r = 0; r < 8; ++r) s0[SP8(8 * t + r)] = v[r];
    __syncwarp();
    {                                          // stage B: Ns=8
        int jm = t & 7;
#pragma unroll
        for (int r = 0; r < 8; ++r) v[r] = s0[SP8(t + 32 * r)];
#pragma unroll
        for (int r = 1; r < 8; ++r) v[r] = twmul<INV>(v[r], tw[4 * jm * r]);
        dft8<INV>(v);
        int base = 8 * (t - jm) + jm;
#pragma unroll
        for (int r = 0; r < 8; ++r) s1[SP8(base + 8 * r)] = v[r];
    }
    __syncwarp();
    {                                          // stage C: Ns=64, radix-4
        float2 a[4], b[4];
#pragma unroll
        for (int r = 0; r < 4; ++r) {
            a[r] = s1[SP8(t + 64 * r)];
            b[r] = s1[SP8(t + 32 + 64 * r)];
        }
#pragma unroll
        for (int r = 1; r < 4; ++r) {
            a[r] = twmul<INV>(a[r], tw[t * r]);
            b[r] = twmul<INV>(b[r], tw[(t + 32) * r]);
        }
        bfly4<INV>(a);
        bfly4<INV>(b);
#pragma unroll
        for (int r = 0; r < 4; ++r) { v[r] = a[r]; v[r + 4] = b[r]; }
    }
}

// ---------------------------------------------------------------------------
// N=256 radix-4 Stockham; lane = 64 threads (2 warps) -> __syncthreads.
// Trailing __syncthreads protects s0 reads from the next call's writes.
// ---------------------------------------------------------------------------
template <bool INV>
__device__ __forceinline__ void fft256_core(float2 v[4], float2* s0, float2* s1,
                                            int t, const float2* tw) {
    bfly4<INV>(v);
    s0[SP(4 * t + 0)] = v[0]; s0[SP(4 * t + 1)] = v[1];
    s0[SP(4 * t + 2)] = v[2]; s0[SP(4 * t + 3)] = v[3];
    __syncthreads();
    {
        int jm = t & 3;
        v[0] = s0[SP(t)];       v[1] = s0[SP(t + 64)];
        v[2] = s0[SP(t + 128)]; v[3] = s0[SP(t + 192)];
        v[1] = twmul<INV>(v[1], tw[16 * jm]);
        v[2] = twmul<INV>(v[2], tw[32 * jm]);
        v[3] = twmul<INV>(v[3], tw[48 * jm]);
        bfly4<INV>(v);
        int d = 4 * (t - jm) + jm;
        s1[SP(d)] = v[0]; s1[SP(d + 4)] = v[1];
        s1[SP(d + 8)] = v[2]; s1[SP(d + 12)] = v[3];
    }
    __syncthreads();
    {
        int jm = t & 15;
        v[0] = s1[SP(t)];       v[1] = s1[SP(t + 64)];
        v[2] = s1[SP(t + 128)]; v[3] = s1[SP(t + 192)];
        v[1] = twmul<INV>(v[1], tw[4 * jm]);
        v[2] = twmul<INV>(v[2], tw[8 * jm]);
        v[3] = twmul<INV>(v[3], tw[12 * jm]);
        bfly4<INV>(v);
        int d = 4 * (t - jm) + jm;
        s0[SP(d)] = v[0]; s0[SP(d + 16)] = v[1];
        s0[SP(d + 32)] = v[2]; s0[SP(d + 48)] = v[3];
    }
    __syncthreads();
    {
        v[0] = s0[SP(t)];       v[1] = s0[SP(t + 64)];
        v[2] = s0[SP(t + 128)]; v[3] = s0[SP(t + 192)];
        v[1] = twmul<INV>(v[1], tw[t]);
        v[2] = twmul<INV>(v[2], tw[2 * t]);
        v[3] = twmul<INV>(v[3], tw[3 * t]);
        bfly4<INV>(v);
    }
    __syncthreads();   // RACE FIX: protect s0 reads from next call's writes
}

// ---------------------------------------------------------------------------
// N=128 radix-4x3 + radix-2; lane = exactly one warp -> __syncwarp only.
// Trailing __syncwarp protects the final-stage reads (ITS safety for loops).
// ---------------------------------------------------------------------------
template <bool INV>
__device__ __forceinline__ void fft128_core(float2 v[4], float2* s0, float2* s1,
                                            int t, const float2* tw) {
    bfly4<INV>(v);
    s0[SP(4 * t + 0)] = v[0]; s0[SP(4 * t + 1)] = v[1];
    s0[SP(4 * t + 2)] = v[2]; s0[SP(4 * t + 3)] = v[3];
    __syncwarp();
    {
        int jm = t & 3;
        v[0] = s0[SP(t)];      v[1] = s0[SP(t + 32)];
        v[2] = s0[SP(t + 64)]; v[3] = s0[SP(t + 96)];
        v[1] = twmul<INV>(v[1], tw[16 * jm]);
        v[2] = twmul<INV>(v[2], tw[32 * jm]);
        v[3] = twmul<INV>(v[3], tw[48 * jm]);
        bfly4<INV>(v);
        int d = 4 * (t - jm) + jm;
        s1[SP(d)] = v[0]; s1[SP(d + 4)] = v[1];
        s1[SP(d + 8)] = v[2]; s1[SP(d + 12)] = v[3];
    }
    __syncwarp();
    {
        int jm = t & 15;
        v[0] = s1[SP(t)];      v[1] = s1[SP(t + 32)];
        v[2] = s1[SP(t + 64)]; v[3] = s1[SP(t + 96)];
        v[1] = twmul<INV>(v[1], tw[4 * jm]);
        v[2] = twmul<INV>(v[2], tw[8 * jm]);
        v[3] = twmul<INV>(v[3], tw[12 * jm]);
        bfly4<INV>(v);
        int d = 4 * (t - jm) + jm;
        s0[SP(d)] = v[0]; s0[SP(d + 16)] = v[1];
        s0[SP(d + 32)] = v[2]; s0[SP(d + 48)] = v[3];
    }
    __syncwarp();
    {
        float2 a0 = s0[SP(t)],      b0 = s0[SP(t + 64)];
        float2 a1 = s0[SP(t + 32)], b1 = s0[SP(t + 96)];
        float2 bw0 = twmul<INV>(b0, tw[2 * t]);
        float2 bw1 = twmul<INV>(b1, tw[2 * (t + 32)]);
        v[0] = cadd(a0, bw0);
        v[2] = csub(a0, bw0);
        v[1] = cadd(a1, bw1);
        v[3] = csub(a1, bw1);
    }
    __syncwarp();      // RACE FIX: protect s0 reads from next call's writes
}

// ---------------------------------------------------------------------------
// FUSED FB: per-plane. Phase 1: 25 row FFTs (N=256) of rolled PSF rows into
// smem Rf. Phase 2: 25-term direct column DFT -> FB^T rows 0..128 (Hermitian).
// ---------------------------------------------------------------------------
__global__ void __launch_bounds__(512, 2)
k_fb(const float* __restrict__ psf, float2* __restrict__ FBt) {
    __shared__ float2 Rf[25][256];
    __shared__ float2 sbuf[8][2 * 272];
    __shared__ float2 stw[256];
    int t = threadIdx.x;      // 0..63
    int g = threadIdx.y;      // 0..7
    int tid = g * 64 + t;
    if (tid < 256) stw[tid] = twval(tid);
    __syncthreads();

    int p = blockIdx.x;
#pragma unroll
    for (int it = 0; it < 4; ++it) {
        int r = g + 8 * it;
        int rr = r < 25 ? r : 24;
        const float* kp = psf + p * 625 + rr * 25;
        float2 v[4];
#pragma unroll
        for (int q = 0; q < 4; ++q) {
            int c = (t + 64 * q + 12) & 255;
            v[q] = make_float2(c < 25 ? kp[c] : 0.f, 0.f);
        }
        fft256_core<false>(v, sbuf[g], sbuf[g] + 272, t, stw);
        if (r < 25) {
            Rf[r][t] = v[0]; Rf[r][t + 64] = v[1];
            Rf[r][t + 128] = v[2]; Rf[r][t + 192] = v[3];
        }
    }
    __syncthreads();

    int v = tid & 255;
    int uc = tid >> 8;
    float2 twr[25];
#pragma unroll
    for (int r = 0; r < 25; ++r)
        twr[r] = stw[(v * (r - 12)) & 255];
    float2* Fp = FBt + p * HSTRIDE;
    for (int u = uc; u <= 128; u += 2) {
        float2 acc = make_float2(0.f, 0.f);
#pragma unroll
        for (int r = 0; r < 25; ++r) {
            float2 a = Rf[r][u];
            acc.x += a.x * twr[r].x - a.y * twr[r].y;
            acc.y += a.x * twr[r].y + a.y * twr[r].x;
        }
        Fp[u * 256 + v] = acc;
    }
}

// ---------------------------------------------------------------------------
// FUSED per-plane 2D FFT of x -> Fx^T[p][u][vh] (XOR-swizzled smem tile).
// ---------------------------------------------------------------------------
__global__ void __launch_bounds__(1024, 1)
k_xfft2(const float* __restrict__ x, float2* __restrict__ Fx) {
    extern __shared__ float2 tile[];          // 128*128 float2 = 128KB dynamic
    __shared__ float2 sbuf[32][2 * 136];
    __shared__ float2 stw[256];
    int t = threadIdx.x;                      // 0..31
    int w = threadIdx.y;                      // 0..31
    int tid = w * 32 + t;
    if (tid < 256) stw[tid] = twval(tid);
    __syncthreads();

    int p = blockIdx.x;
    const float* xp = x + p * 16384;

#pragma unroll
    for (int it = 0; it < 2; ++it) {
        int j = w + 32 * it;
        const float* xa = xp + j * 256;
        float2 v[4];
#pragma unroll
        for (int q = 0; q < 4; ++q)
            v[q] = make_float2(xa[t + 32 * q], xa[128 + t + 32 * q]);
        fft128_core<false>(v, sbuf[w], sbuf[w] + 136, t, stw);
        float2* s0 = sbuf[w];
#pragma unroll
        for (int q = 0; q < 4; ++q) s0[SP(t + 32 * q)] = v[q];
        __syncwarp();
        int ya = 2 * j, yb = 2 * j + 1;
        int sa = ya & 31, sb = yb & 31;
#pragma unroll
        for (int q = 0; q < 4; ++q) {
            int k = t + 32 * q;
            float2 Zk = s0[SP(k)];
            float2 Zm = s0[SP((128 - k) & 127)];
            tile[ya * 128 + (k ^ sa)] =
                make_float2(0.5f * (Zk.x + Zm.x), 0.5f * (Zk.y - Zm.y));
            tile[yb * 128 + (k ^ sb)] =
                make_float2(0.5f * (Zk.y + Zm.y), 0.5f * (Zm.x - Zk.x));
        }
        __syncwarp();
    }
    __syncthreads();

    float2* Fp = Fx + p * 16384;
#pragma unroll
    for (int rep = 0; rep < 4; ++rep) {
        int u = w + 32 * rep;
        float2 v[4];
#pragma unroll
        for (int q = 0; q < 4; ++q) {
            int y = t + 32 * q;
            v[q] = tile[y * 128 + (u ^ (y & 31))];
        }
        fft128_core<false>(v, sbuf[w], sbuf[w] + 136, t, stw);
        float2* d = Fp + u * 128;
        d[t] = v[0]; d[t + 32] = v[1]; d[t + 64] = v[2]; d[t + 96] = v[3];
    }
}

// ---------------------------------------------------------------------------
// FUSED solve + inverse-256, cancellation-free, WARP-LOCAL FFT:
// one spectrum row A per warp (32 lanes, 8 regs), radix 8-8-4, no block syncs.
//   S = mean_q(FB_q P_q),  W = mean_q|FB_q|^2
//   FX_q = Fx * ( P_q + conj(FB_q) * (1-S)/(W+be) )
// ---------------------------------------------------------------------------
__global__ void __launch_bounds__(256)
k_solve(const float* __restrict__ alpha) {
    __shared__ float2 sA[8][328];
    __shared__ float2 sB[8][328];
    __shared__ float2 stw[256];
    int t = threadIdx.x;       // 0..31
    int ry = threadIdx.y;      // 0..7
    int tid = ry * 32 + t;
    stw[tid] = twval(tid);
    __syncthreads();

    int p = blockIdx.y;
    int A = blockIdx.x * 8 + ry;               // 0..135; rows >128 idle-write
    int AA = A <= 128 ? A : 128;
    bool hi = (AA == 128);
    int vv = hi ? 0 : AA;

    float a = alpha[p & (NCH - 1)];
    float be = 1.f / (1.f + expf(9.f - a)) + 1e-3f;

    const float2* FBp = g_SA + p * HSTRIDE;
    const float2* FBd = FBp + vv * 256;
    const float2* FBm = FBp + (128 - vv) * 256;
    const float2* Fxr = g_SC + (p << 14) + (vv << 7);

    float2 twv0 = stw[vv], twv1 = stw[vv + 128];
    float2 pv0 = make_float2(1.f + twv0.x, twv0.y);
    float2 pv1 = make_float2(1.f + twv1.x, twv1.y);

    float2 v[8];
#pragma unroll
    for (int q = 0; q < 4; ++q) {
        int u = t + 32 * q;                    // < 128
        float2 fx = Fxr[u];

        float2 FB[4];
        FB[0] = FBd[u];
        FB[1] = FBd[u + 128];
        if (vv == 0) {
            FB[2] = FBm[u];
            FB[3] = FBm[u + 128];
        } else {
            float2 t0 = FBm[(256 - u) & 255];
            float2 t1 = FBm[128 - u];
            FB[2] = make_float2(t0.x, -t0.y);
            FB[3] = make_float2(t1.x, -t1.y);
        }

        float2 twu0 = stw[u], twu1 = stw[u + 128];
        float2 pu0 = make_float2(1.f + twu0.x, twu0.y);
        float2 pu1 = make_float2(1.f + twu1.x, twu1.y);

        float2 P[4];
        P[0] = cmulf(pu0, pv0);
        P[1] = cmulf(pu1, pv0);
        P[2] = cmulf(pu0, pv1);
        P[3] = cmulf(pu1, pv1);

        float2 S = make_float2(0.f, 0.f);
        float W = 0.f;
#pragma unroll
        for (int q2 = 0; q2 < 4; ++q2) {
            float2 fb = FB[q2];
            S.x += fb.x * P[q2].x - fb.y * P[q2].y;
            S.y += fb.x * P[q2].y + fb.y * P[q2].x;
            W += fb.x * fb.x + fb.y * fb.y;
        }
        S.x *= 0.25f; S.y *= 0.25f; W *= 0.25f;
        float inv = 1.f / (W + be);
        float2 c = make_float2((1.f - S.x) * inv, -S.y * inv);

        int qlo = hi ? 2 : 0;
#pragma unroll
        for (int j = 0; j < 2; ++j) {
            int qq = qlo + j;
            float2 m = make_float2(
                P[qq].x + FB[qq].x * c.x + FB[qq].y * c.y,
                P[qq].y + FB[qq].x * c.y - FB[qq].y * c.x);
            v[q + 4 * j] = cmulf(fx, m);   // FX[t+32q], FX[t+32q+128]
        }
    }

    fft256_w<true>(v, sA[ry], sB[ry], t, stw);

    if (A <= 128) {
        float2* d = g_SB + p * HSTRIDE + A * 256;
#pragma unroll
        for (int r = 0; r < 4; ++r) {
            d[t + 64 * r]      = v[r];
            d[t + 32 + 64 * r] = v[r + 4];
        }
    }
}

// ---------------------------------------------------------------------------
// Final: fused transpose + Hermitian-packed real inverse along width.
// ---------------------------------------------------------------------------
__global__ void k_final(const float2* __restrict__ G, float2* __restrict__ out2) {
    __shared__ float2 tile[129][17];
    __shared__ float2 sbuf[8][2 * 136];
    __shared__ float2 stw[256];
    int t = threadIdx.x, f = threadIdx.y;      // (32,8)
    int tid = f * 32 + t;
    stw[tid] = twval(tid);
    int p = blockIdx.y, x0 = blockIdx.x * 16;
    const float2* Gp = G + p * HSTRIDE;
#pragma unroll
    for (int it = 0; it < 9; ++it) {
        int idx = it * 256 + tid;
        int A = idx >> 4, ff = idx & 15;
        if (A < 129) tile[A][ff] = Gp[A * 256 + x0 + ff];
    }
    __syncthreads();
    const float s = 1.0f / 65536.0f;
#pragma unroll
    for (int rep = 0; rep < 2; ++rep) {
        int fc = f + 8 * rep;
        float2 v[4];
#pragma unroll
        for (int q = 0; q < 4; ++q) {
            int k = t + 32 * q;
            float2 hk = tile[k][fc];
            float2 hm = tile[128 - k][fc];
            float2 c = stw[k];
            float Ax = hk.x + hm.x, Ay = hk.y - hm.y;
            float Bx = hk.x - hm.x, By = hk.y + hm.y;
            float cr = c.x * Bx + c.y * By;
            float ci = c.x * By - c.y * Bx;
            v[q] = make_float2(Ax - ci, Ay + cr);
        }
        fft128_core<true>(v, sbuf[f], sbuf[f] + 136, t, stw);
        float2* d = out2 + ((p << 8) + x0 + fc) * 128;
#pragma unroll
        for (int q = 0; q < 4; ++q)
            d[t + 32 * q] = make_float2(v[q].x * s, v[q].y * s);
    }
}

extern "C" void kernel_launch(void* const* d_in, const int* in_sizes, int n_in,
                              void* d_out, int out_size) {
    const float* x     = (const float*)d_in[0];
    const float* psf   = (const float*)d_in[1];
    const float* alpha = (const float*)d_in[2];
    float* out = (float*)d_out;

    float2 *SA, *SB, *SC;
    cudaGetSymbolAddress((void**)&SA, g_SA);
    cudaGetSymbolAddress((void**)&SB, g_SB);
    cudaGetSymbolAddress((void**)&SC, g_SC);

    // 1) FB^T half (rows 0..128) -> SA
    k_fb<<<NPLANES, dim3(64, 8)>>>(psf, SA);

    // 2) Fx^T[p][u][vh] -> SC
    cudaFuncSetAttribute(k_xfft2, cudaFuncAttributeMaxDynamicSharedMemorySize,
                         128 * 128 * sizeof(float2));
    k_xfft2<<<NPLANES, dim3(32, 32), 128 * 128 * sizeof(float2)>>>(x, SC);

    // 3) Cancellation-free solve + WARP-LOCAL inverse-256 -> SB holds G half
    k_solve<<<dim3(17, NPLANES), dim3(32, 8)>>>(alpha);

    // 4) Hermitian-packed real inverse along width -> out
    k_final<<<dim3(16, NPLANES), dim3(32, 8)>>>(SB, (float2*)out);
}

// round 16
// speedup vs baseline: 1.4573x; 1.0192x over previous
#include <cuda_runtime.h>
#include <math.h>

// Shapes fixed: x (4,64,128,128), k (4,64,25,25), alpha (1,64,1,1), sf=2.
// Output (4,64,256,256) fp32.
#define NPLANES 256
#define NCH 64
#define HSTRIDE (129 * 256)   // half-spectrum plane stride (rows 0..128)

__device__ float2 g_SA[NPLANES * HSTRIDE];     // FB half
__device__ float2 g_SB[NPLANES * HSTRIDE];     // G half
__device__ float2 g_SC[NPLANES * 128 * 128];   // Fx^T

#define SP(i) ((i) + ((i) >> 4))
#define SP8(i) ((i) + ((i) >> 3))

// in-kernel twiddle: e^{-2 pi i t/256}
__device__ __forceinline__ float2 twval(int t) {
    float s, c;
    sincospif(-(float)t * (1.0f / 128.0f), &s, &c);
    return make_float2(c, s);
}

__device__ __forceinline__ float2 cmulf(float2 a, float2 b) {
    return make_float2(a.x * b.x - a.y * b.y, a.x * b.y + a.y * b.x);
}
__device__ __forceinline__ float2 cadd(float2 a, float2 b) {
    return make_float2(a.x + b.x, a.y + b.y);
}
__device__ __forceinline__ float2 csub(float2 a, float2 b) {
    return make_float2(a.x - b.x, a.y - b.y);
}

template <bool INV>
__device__ __forceinline__ float2 twmul(float2 a, float2 w) {
    float wy = INV ? -w.y : w.y;
    return make_float2(a.x * w.x - a.y * wy, a.x * wy + a.y * w.x);
}

// complex mul by compile-time constant (forward sign); conj for INV
template <bool INV>
__device__ __forceinline__ float2 wmulc(float2 a, float cr, float ci_fwd) {
    float ci = INV ? -ci_fwd : ci_fwd;
    return make_float2(a.x * cr - a.y * ci, a.x * ci + a.y * cr);
}

template <bool INV>
__device__ __forceinline__ void bfly4(float2 v[4]) {
    float2 t0 = cadd(v[0], v[2]);
    float2 t1 = csub(v[0], v[2]);
    float2 t2 = cadd(v[1], v[3]);
    float2 t3 = csub(v[1], v[3]);
    v[0] = cadd(t0, t2);
    v[2] = csub(t0, t2);
    if (!INV) {
        v[1] = make_float2(t1.x + t3.y, t1.y - t3.x);
        v[3] = make_float2(t1.x - t3.y, t1.y + t3.x);
    } else {
        v[1] = make_float2(t1.x - t3.y, t1.y + t3.x);
        v[3] = make_float2(t1.x + t3.y, t1.y - t3.x);
    }
}

// natural-order DFT-8 in registers (DIT even/odd split)
template <bool INV>
__device__ __forceinline__ void dft8(float2 v[8]) {
    const float R2 = 0.7071067811865476f;
    float2 e[4] = {v[0], v[2], v[4], v[6]};
    float2 o[4] = {v[1], v[3], v[5], v[7]};
    bfly4<INV>(e);
    bfly4<INV>(o);
    o[1] = wmulc<INV>(o[1],  R2, -R2);   // W8^1
    o[2] = wmulc<INV>(o[2], 0.f, -1.f);  // W8^2
    o[3] = wmulc<INV>(o[3], -R2, -R2);   // W8^3
#pragma unroll
    for (int k = 0; k < 4; ++k) {
        v[k]     = cadd(e[k], o[k]);
        v[k + 4] = csub(e[k], o[k]);
    }
}

// ---------------------------------------------------------------------------
// Warp-local FFT-256: radix 8 -> 8 -> 4 Stockham, 32 threads/row,
// 8 regs/thread, 2 smem exchanges, __syncwarp only.
// Input  v[r] = x[t + 32r];  Output v[r] = X[t + 64r], v[r+4] = X[t+32+64r].
// Safe to call back-to-back on the same buffers: the stage-A syncwarp of the
// next call orders prior stage-C reads of s1 before the next stage-B writes.
// ---------------------------------------------------------------------------
template <bool INV>
__device__ __forceinline__ void fft256_w(float2 v[8], float2* s0, float2* s1,
                                         int t, const float2* tw) {
    dft8<INV>(v);                              // stage A: Ns=1
#pragma unroll
    for (int r = 0; r < 8; ++r) s0[SP8(8 * t + r)] = v[r];
    __syncwarp();
    {                                          // stage B: Ns=8
        int jm = t & 7;
#pragma unroll
        for (int r = 0; r < 8; ++r) v[r] = s0[SP8(t + 32 * r)];
#pragma unroll
        for (int r = 1; r < 8; ++r) v[r] = twmul<INV>(v[r], tw[4 * jm * r]);
        dft8<INV>(v);
        int base = 8 * (t - jm) + jm;
#pragma unroll
        for (int r = 0; r < 8; ++r) s1[SP8(base + 8 * r)] = v[r];
    }
    __syncwarp();
    {                                          // stage C: Ns=64, radix-4
        float2 a[4], b[4];
#pragma unroll
        for (int r = 0; r < 4; ++r) {
            a[r] = s1[SP8(t + 64 * r)];
            b[r] = s1[SP8(t + 32 + 64 * r)];
        }
#pragma unroll
        for (int r = 1; r < 4; ++r) {
            a[r] = twmul<INV>(a[r], tw[t * r]);
            b[r] = twmul<INV>(b[r], tw[(t + 32) * r]);
        }
        bfly4<INV>(a);
        bfly4<INV>(b);
#pragma unroll
        for (int r = 0; r < 4; ++r) { v[r] = a[r]; v[r + 4] = b[r]; }
    }
    __syncwarp();      // protect s1 reads from any subsequent writes
}

// ---------------------------------------------------------------------------
// N=128 radix-4x3 + radix-2; lane = exactly one warp -> __syncwarp only.
// Trailing __syncwarp protects the final-stage reads (ITS safety for loops).
// ---------------------------------------------------------------------------
template <bool INV>
__device__ __forceinline__ void fft128_core(float2 v[4], float2* s0, float2* s1,
                                            int t, const float2* tw) {
    bfly4<INV>(v);
    s0[SP(4 * t + 0)] = v[0]; s0[SP(4 * t + 1)] = v[1];
    s0[SP(4 * t + 2)] = v[2]; s0[SP(4 * t + 3)] = v[3];
    __syncwarp();
    {
        int jm = t & 3;
        v[0] = s0[SP(t)];      v[1] = s0[SP(t + 32)];
        v[2] = s0[SP(t + 64)]; v[3] = s0[SP(t + 96)];
        v[1] = twmul<INV>(v[1], tw[16 * jm]);
        v[2] = twmul<INV>(v[2], tw[32 * jm]);
        v[3] = twmul<INV>(v[3], tw[48 * jm]);
        bfly4<INV>(v);
        int d = 4 * (t - jm) + jm;
        s1[SP(d)] = v[0]; s1[SP(d + 4)] = v[1];
        s1[SP(d + 8)] = v[2]; s1[SP(d + 12)] = v[3];
    }
    __syncwarp();
    {
        int jm = t & 15;
        v[0] = s1[SP(t)];      v[1] = s1[SP(t + 32)];
        v[2] = s1[SP(t + 64)]; v[3] = s1[SP(t + 96)];
        v[1] = twmul<INV>(v[1], tw[4 * jm]);
        v[2] = twmul<INV>(v[2], tw[8 * jm]);
        v[3] = twmul<INV>(v[3], tw[12 * jm]);
        bfly4<INV>(v);
        int d = 4 * (t - jm) + jm;
        s0[SP(d)] = v[0]; s0[SP(d + 16)] = v[1];
        s0[SP(d + 32)] = v[2]; s0[SP(d + 48)] = v[3];
    }
    __syncwarp();
    {
        float2 a0 = s0[SP(t)],      b0 = s0[SP(t + 64)];
        float2 a1 = s0[SP(t + 32)], b1 = s0[SP(t + 96)];
        float2 bw0 = twmul<INV>(b0, tw[2 * t]);
        float2 bw1 = twmul<INV>(b1, tw[2 * (t + 32)]);
        v[0] = cadd(a0, bw0);
        v[2] = csub(a0, bw0);
        v[1] = cadd(a1, bw1);
        v[3] = csub(a1, bw1);
    }
    __syncwarp();      // RACE FIX: protect s0 reads from next call's writes
}

// ---------------------------------------------------------------------------
// FUSED FB: per-plane. Phase 1: 25 row FFTs (N=256) of rolled PSF rows into
// smem Rf — WARP-LOCAL (one warp per row, no block syncs).
// Phase 2: 25-term direct column DFT -> FB^T rows 0..128 (Hermitian).
// ---------------------------------------------------------------------------
__global__ void __launch_bounds__(512)
k_fb(const float* __restrict__ psf, float2* __restrict__ FBt) {
    __shared__ float2 Rf[25][256];
    __shared__ float2 sA[16][288];
    __shared__ float2 sB[16][288];
    __shared__ float2 stw[256];
    int t = threadIdx.x;      // 0..31
    int g = threadIdx.y;      // 0..15
    int tid = g * 32 + t;
    if (tid < 256) stw[tid] = twval(tid);
    __syncthreads();

    int p = blockIdx.x;
    // Phase 1: warp g handles rows {g, g+16} (rows >= 25 skipped entirely)
#pragma unroll
    for (int it = 0; it < 2; ++it) {
        int r = g + 16 * it;
        if (r < 25) {
            const float* kp = psf + p * 625 + r * 25;
            float2 v[8];
#pragma unroll
            for (int i = 0; i < 8; ++i) {
                int c = (t + 32 * i + 12) & 255;
                v[i] = make_float2(c < 25 ? kp[c] : 0.f, 0.f);
            }
            fft256_w<false>(v, sA[g], sB[g], t, stw);
#pragma unroll
            for (int j = 0; j < 4; ++j) {
                Rf[r][t + 64 * j]      = v[j];
                Rf[r][t + 32 + 64 * j] = v[j + 4];
            }
        }
    }
    __syncthreads();

    // Phase 2: FB^T[u][v] = sum_r Rf[r][u] * tw[(v*(r-12)) mod 256]
    int v = tid & 255;
    int uc = tid >> 8;        // 0..1
    float2 twr[25];
#pragma unroll
    for (int r = 0; r < 25; ++r)
        twr[r] = stw[(v * (r - 12)) & 255];
    float2* Fp = FBt + p * HSTRIDE;
    for (int u = uc; u <= 128; u += 2) {
        float2 acc = make_float2(0.f, 0.f);
#pragma unroll
        for (int r = 0; r < 25; ++r) {
            float2 a = Rf[r][u];
            acc.x += a.x * twr[r].x - a.y * twr[r].y;
            acc.y += a.x * twr[r].y + a.y * twr[r].x;
        }
        Fp[u * 256 + v] = acc;
    }
}

// ---------------------------------------------------------------------------
// FUSED per-plane 2D FFT of x -> Fx^T[p][u][vh] (XOR-swizzled smem tile).
// ---------------------------------------------------------------------------
__global__ void __launch_bounds__(1024, 1)
k_xfft2(const float* __restrict__ x, float2* __restrict__ Fx) {
    extern __shared__ float2 tile[];          // 128*128 float2 = 128KB dynamic
    __shared__ float2 sbuf[32][2 * 136];
    __shared__ float2 stw[256];
    int t = threadIdx.x;                      // 0..31
    int w = threadIdx.y;                      // 0..31
    int tid = w * 32 + t;
    if (tid < 256) stw[tid] = twval(tid);
    __syncthreads();

    int p = blockIdx.x;
    const float* xp = x + p * 16384;

#pragma unroll
    for (int it = 0; it < 2; ++it) {
        int j = w + 32 * it;
        const float* xa = xp + j * 256;
        float2 v[4];
#pragma unroll
        for (int q = 0; q < 4; ++q)
            v[q] = make_float2(xa[t + 32 * q], xa[128 + t + 32 * q]);
        fft128_core<false>(v, sbuf[w], sbuf[w] + 136, t, stw);
        float2* s0 = sbuf[w];
#pragma unroll
        for (int q = 0; q < 4; ++q) s0[SP(t + 32 * q)] = v[q];
        __syncwarp();
        int ya = 2 * j, yb = 2 * j + 1;
        int sa = ya & 31, sb = yb & 31;
#pragma unroll
        for (int q = 0; q < 4; ++q) {
            int k = t + 32 * q;
            float2 Zk = s0[SP(k)];
            float2 Zm = s0[SP((128 - k) & 127)];
            tile[ya * 128 + (k ^ sa)] =
                make_float2(0.5f * (Zk.x + Zm.x), 0.5f * (Zk.y - Zm.y));
            tile[yb * 128 + (k ^ sb)] =
                make_float2(0.5f * (Zk.y + Zm.y), 0.5f * (Zm.x - Zk.x));
        }
        __syncwarp();
    }
    __syncthreads();

    float2* Fp = Fx + p * 16384;
#pragma unroll
    for (int rep = 0; rep < 4; ++rep) {
        int u = w + 32 * rep;
        float2 v[4];
#pragma unroll
        for (int q = 0; q < 4; ++q) {
            int y = t + 32 * q;
            v[q] = tile[y * 128 + (u ^ (y & 31))];
        }
        fft128_core<false>(v, sbuf[w], sbuf[w] + 136, t, stw);
        float2* d = Fp + u * 128;
        d[t] = v[0]; d[t + 32] = v[1]; d[t + 64] = v[2]; d[t + 96] = v[3];
    }
}

// ---------------------------------------------------------------------------
// FUSED solve + inverse-256, cancellation-free, WARP-LOCAL FFT:
// one spectrum row A per warp (32 lanes, 8 regs), radix 8-8-4, no block syncs.
//   S = mean_q(FB_q P_q),  W = mean_q|FB_q|^2
//   FX_q = Fx * ( P_q + conj(FB_q) * (1-S)/(W+be) )
// ---------------------------------------------------------------------------
__global__ void __launch_bounds__(256)
k_solve(const float* __restrict__ alpha) {
    __shared__ float2 sA[8][328];
    __shared__ float2 sB[8][328];
    __shared__ float2 stw[256];
    int t = threadIdx.x;       // 0..31
    int ry = threadIdx.y;      // 0..7
    int tid = ry * 32 + t;
    stw[tid] = twval(tid);
    __syncthreads();

    int p = blockIdx.y;
    int A = blockIdx.x * 8 + ry;               // 0..135; rows >128 idle-write
    int AA = A <= 128 ? A : 128;
    bool hi = (AA == 128);
    int vv = hi ? 0 : AA;

    float a = alpha[p & (NCH - 1)];
    float be = 1.f / (1.f + expf(9.f - a)) + 1e-3f;

    const float2* FBp = g_SA + p * HSTRIDE;
    const float2* FBd = FBp + vv * 256;
    const float2* FBm = FBp + (128 - vv) * 256;
    const float2* Fxr = g_SC + (p << 14) + (vv << 7);

    float2 twv0 = stw[vv], twv1 = stw[vv + 128];
    float2 pv0 = make_float2(1.f + twv0.x, twv0.y);
    float2 pv1 = make_float2(1.f + twv1.x, twv1.y);

    float2 v[8];
#pragma unroll
    for (int q = 0; q < 4; ++q) {
        int u = t + 32 * q;                    // < 128
        float2 fx = Fxr[u];

        float2 FB[4];
        FB[0] = FBd[u];
        FB[1] = FBd[u + 128];
        if (vv == 0) {
            FB[2] = FBm[u];
            FB[3] = FBm[u + 128];
        } else {
            float2 t0 = FBm[(256 - u) & 255];
            float2 t1 = FBm[128 - u];
            FB[2] = make_float2(t0.x, -t0.y);
            FB[3] = make_float2(t1.x, -t1.y);
        }

        float2 twu0 = stw[u], twu1 = stw[u + 128];
        float2 pu0 = make_float2(1.f + twu0.x, twu0.y);
        float2 pu1 = make_float2(1.f + twu1.x, twu1.y);

        float2 P[4];
        P[0] = cmulf(pu0, pv0);
        P[1] = cmulf(pu1, pv0);
        P[2] = cmulf(pu0, pv1);
        P[3] = cmulf(pu1, pv1);

        float2 S = make_float2(0.f, 0.f);
        float W = 0.f;
#pragma unroll
        for (int q2 = 0; q2 < 4; ++q2) {
            float2 fb = FB[q2];
            S.x += fb.x * P[q2].x - fb.y * P[q2].y;
            S.y += fb.x * P[q2].y + fb.y * P[q2].x;
            W += fb.x * fb.x + fb.y * fb.y;
        }
        S.x *= 0.25f; S.y *= 0.25f; W *= 0.25f;
        float inv = 1.f / (W + be);
        float2 c = make_float2((1.f - S.x) * inv, -S.y * inv);

        int qlo = hi ? 2 : 0;
#pragma unroll
        for (int j = 0; j < 2; ++j) {
            int qq = qlo + j;
            float2 m = make_float2(
                P[qq].x + FB[qq].x * c.x + FB[qq].y * c.y,
                P[qq].y + FB[qq].x * c.y - FB[qq].y * c.x);
            v[q + 4 * j] = cmulf(fx, m);   // FX[t+32q], FX[t+32q+128]
        }
    }

    fft256_w<true>(v, sA[ry], sB[ry], t, stw);

    if (A <= 128) {
        float2* d = g_SB + p * HSTRIDE + A * 256;
#pragma unroll
        for (int r = 0; r < 4; ++r) {
            d[t + 64 * r]      = v[r];
            d[t + 32 + 64 * r] = v[r + 4];
        }
    }
}

// ---------------------------------------------------------------------------
// Final: fused transpose + Hermitian-packed real inverse along width.
// ---------------------------------------------------------------------------
__global__ void k_final(const float2* __restrict__ G, float2* __restrict__ out2) {
    __shared__ float2 tile[129][17];
    __shared__ float2 sbuf[8][2 * 136];
    __shared__ float2 stw[256];
    int t = threadIdx.x, f = threadIdx.y;      // (32,8)
    int tid = f * 32 + t;
    stw[tid] = twval(tid);
    int p = blockIdx.y, x0 = blockIdx.x * 16;
    const float2* Gp = G + p * HSTRIDE;
#pragma unroll
    for (int it = 0; it < 9; ++it) {
        int idx = it * 256 + tid;
        int A = idx >> 4, ff = idx & 15;
        if (A < 129) tile[A][ff] = Gp[A * 256 + x0 + ff];
    }
    __syncthreads();
    const float s = 1.0f / 65536.0f;
#pragma unroll
    for (int rep = 0; rep < 2; ++rep) {
        int fc = f + 8 * rep;
        float2 v[4];
#pragma unroll
        for (int q = 0; q < 4; ++q) {
            int k = t + 32 * q;
            float2 hk = tile[k][fc];
            float2 hm = tile[128 - k][fc];
            float2 c = stw[k];
            float Ax = hk.x + hm.x, Ay = hk.y - hm.y;
            float Bx = hk.x - hm.x, By = hk.y + hm.y;
            float cr = c.x * Bx + c.y * By;
            float ci = c.x * By - c.y * Bx;
            v[q] = make_float2(Ax - ci, Ay + cr);
        }
        fft128_core<true>(v, sbuf[f], sbuf[f] + 136, t, stw);
        float2* d = out2 + ((p << 8) + x0 + fc) * 128;
#pragma unroll
        for (int q = 0; q < 4; ++q)
            d[t + 32 * q] = make_float2(v[q].x * s, v[q].y * s);
    }
}

extern "C" void kernel_launch(void* const* d_in, const int* in_sizes, int n_in,
                              void* d_out, int out_size) {
    const float* x     = (const float*)d_in[0];
    const float* psf   = (const float*)d_in[1];
    const float* alpha = (const float*)d_in[2];
    float* out = (float*)d_out;

    float2 *SA, *SB, *SC;
    cudaGetSymbolAddress((void**)&SA, g_SA);
    cudaGetSymbolAddress((void**)&SB, g_SB);
    cudaGetSymbolAddress((void**)&SC, g_SC);

    // 1) FB^T half (rows 0..128) -> SA  (warp-local row FFTs + column DFT)
    k_fb<<<NPLANES, dim3(32, 16)>>>(psf, SA);

    // 2) Fx^T[p][u][vh] -> SC
    cudaFuncSetAttribute(k_xfft2, cudaFuncAttributeMaxDynamicSharedMemorySize,
                         128 * 128 * sizeof(float2));
    k_xfft2<<<NPLANES, dim3(32, 32), 128 * 128 * sizeof(float2)>>>(x, SC);

    // 3) Cancellation-free solve + WARP-LOCAL inverse-256 -> SB holds G half
    k_solve<<<dim3(17, NPLANES), dim3(32, 8)>>>(alpha);

    // 4) Hermitian-packed real inverse along width -> out
    k_final<<<dim3(16, NPLANES), dim3(32, 8)>>>(SB, (float2*)out);
}